// round 10
// baseline (speedup 1.0000x reference)
#include <cuda_runtime.h>
#include <math.h>

#define NPT 1024
#define FDIM 128
#define HDIM 128
#define NNTOT (NPT*NPT)
#define EPS 1e-5f

// ---------------- scratch (device globals; no allocations) ----------------
__device__ float g_A[NPT*HDIM];
__device__ float g_B[NPT*HDIM];
__device__ float g_PT[HDIM*NPT];     // P transposed: [h][j]
__device__ float g_Q[NPT*HDIM];      // [i][h]
__device__ float g_sc1[HDIM], g_off1[HDIM];
__device__ float g_W2T[HDIM*HDIM];   // [h][k]
__device__ float g_tsum[HDIM], g_tsq[HDIM];
__device__ float g_sc2[HDIM], g_off2[HDIM];
__device__ float g_T[(size_t)NNTOT*HDIM];   // 512 MB: t[i*N+j][k]
__device__ float g_L[NNTOT];                // logits

// ---------------- K1: A = x@Wa^T, B = x@Wb^T -------------------------------
__global__ void k_ab(const float* __restrict__ x, const float* __restrict__ W1) {
    __shared__ float xs[FDIM];
    int j = blockIdx.x;
    int h = threadIdx.x;          // 128 threads
    xs[h] = x[j*FDIM + h];
    __syncthreads();
    const float* wr = W1 + h*(2*FDIM);
    float a = 0.f, b = 0.f;
#pragma unroll 8
    for (int f = 0; f < FDIM; f++) {
        float xv = xs[f];
        a = fmaf(xv, wr[f], a);
        b = fmaf(xv, wr[FDIM + f], b);
    }
    g_A[j*HDIM + h] = a;
    g_B[j*HDIM + h] = b;
}

// ---------------- K2: BN1 stats (exact decomposition) ----------------------
// mean(A_j+B_i+b1) over the product grid = mean_j A + mean_i B + b1
// var = Var(A) + Var(B)   (cross term vanishes exactly on the product grid)
__global__ void k_bn1(const float* __restrict__ b1, const float* __restrict__ g1,
                      const float* __restrict__ be1) {
    int h = blockIdx.x;
    int t = threadIdx.x;          // 256 threads
    float sa = 0.f, sa2 = 0.f, sb = 0.f, sb2 = 0.f;
    for (int j = t; j < NPT; j += 256) {
        float a = g_A[j*HDIM + h]; sa += a; sa2 += a*a;
        float b = g_B[j*HDIM + h]; sb += b; sb2 += b*b;
    }
    __shared__ float red[4][256];
    red[0][t] = sa; red[1][t] = sa2; red[2][t] = sb; red[3][t] = sb2;
    __syncthreads();
    for (int s = 128; s > 0; s >>= 1) {
        if (t < s) {
#pragma unroll
            for (int c = 0; c < 4; c++) red[c][t] += red[c][t + s];
        }
        __syncthreads();
    }
    if (t == 0) {
        float ma = red[0][0] * (1.f/NPT), mb = red[2][0] * (1.f/NPT);
        float va = red[1][0] * (1.f/NPT) - ma*ma;
        float vb = red[3][0] * (1.f/NPT) - mb*mb;
        float m1  = ma + mb + b1[h];
        float sc  = g1[h] * rsqrtf(va + vb + EPS);
        g_sc1[h]  = sc;
        g_off1[h] = (b1[h] - m1) * sc + be1[h];
    }
}

// ---------------- K3: fold BN1 into P^T, Q; transpose W2; zero stats -------
__global__ void k_prep(const float* __restrict__ W2) {
    int idx = blockIdx.x*256 + threadIdx.x;
    if (idx < NPT*HDIM) {
        int j = idx / HDIM, h = idx % HDIM;
        float sc = g_sc1[h];
        g_PT[h*NPT + j] = g_A[idx] * sc;
        g_Q[idx]        = g_B[idx] * sc + g_off1[h];
    }
    if (idx < HDIM*HDIM) {
        int k = idx / HDIM, h = idx % HDIM;
        g_W2T[h*HDIM + k] = W2[idx];
    }
    if (idx < HDIM) { g_tsum[idx] = 0.f; g_tsq[idx] = 0.f; }
}

// ---------------- K4: heavy pass — t = relu(P+Q) @ W2^T, write T, stats ----
// CTA: 128 samples (fixed i, j-range of 128) x 128 k, BK=16, 8x8 per thread.
// Double-buffered smem: global loads for tile n+1 overlap compute on tile n.
__global__ __launch_bounds__(256, 2) void k_pass1() {
    const int i  = blockIdx.y;
    const int j0 = blockIdx.x * 128;
    __shared__ float Rs[2][16][132];
    __shared__ float Ws[2][16][132];
    __shared__ float Qs[HDIM];
    const int tid = threadIdx.x;
    if (tid < HDIM) Qs[tid] = g_Q[i*HDIM + tid];
    const int tx = tid & 15;          // k-dim
    const int ty = tid >> 4;          // sample-dim
    const int lr = ty;                // load row 0..15
    const int lc = (tid & 15) * 8;    // load col 0..120

    float acc[8][8];
#pragma unroll
    for (int m = 0; m < 8; m++)
#pragma unroll
        for (int n = 0; n < 8; n++) acc[m][n] = 0.f;

    // prologue: load tile h0=0
    float4 p0 = *(const float4*)&g_PT[lr*NPT + j0 + lc];
    float4 p1 = *(const float4*)&g_PT[lr*NPT + j0 + lc + 4];
    float4 w0 = *(const float4*)&g_W2T[lr*HDIM + lc];
    float4 w1 = *(const float4*)&g_W2T[lr*HDIM + lc + 4];
    __syncthreads();                  // Qs visible
    {
        float qv = Qs[lr];
        Rs[0][lr][lc+0] = fmaxf(p0.x + qv, 0.f);
        Rs[0][lr][lc+1] = fmaxf(p0.y + qv, 0.f);
        Rs[0][lr][lc+2] = fmaxf(p0.z + qv, 0.f);
        Rs[0][lr][lc+3] = fmaxf(p0.w + qv, 0.f);
        Rs[0][lr][lc+4] = fmaxf(p1.x + qv, 0.f);
        Rs[0][lr][lc+5] = fmaxf(p1.y + qv, 0.f);
        Rs[0][lr][lc+6] = fmaxf(p1.z + qv, 0.f);
        Rs[0][lr][lc+7] = fmaxf(p1.w + qv, 0.f);
        Ws[0][lr][lc+0] = w0.x; Ws[0][lr][lc+1] = w0.y;
        Ws[0][lr][lc+2] = w0.z; Ws[0][lr][lc+3] = w0.w;
        Ws[0][lr][lc+4] = w1.x; Ws[0][lr][lc+5] = w1.y;
        Ws[0][lr][lc+6] = w1.z; Ws[0][lr][lc+7] = w1.w;
    }
    __syncthreads();

    int buf = 0;
    for (int h0 = 16; h0 <= HDIM; h0 += 16) {
        const bool more = (h0 < HDIM);
        if (more) {
            p0 = *(const float4*)&g_PT[(h0 + lr)*NPT + j0 + lc];
            p1 = *(const float4*)&g_PT[(h0 + lr)*NPT + j0 + lc + 4];
            w0 = *(const float4*)&g_W2T[(h0 + lr)*HDIM + lc];
            w1 = *(const float4*)&g_W2T[(h0 + lr)*HDIM + lc + 4];
        }
#pragma unroll
        for (int kk = 0; kk < 16; kk++) {
            float a[8], b[8];
            *(float4*)&a[0] = *(const float4*)&Rs[buf][kk][ty*8];
            *(float4*)&a[4] = *(const float4*)&Rs[buf][kk][ty*8 + 4];
            *(float4*)&b[0] = *(const float4*)&Ws[buf][kk][tx*8];
            *(float4*)&b[4] = *(const float4*)&Ws[buf][kk][tx*8 + 4];
#pragma unroll
            for (int m = 0; m < 8; m++)
#pragma unroll
                for (int n = 0; n < 8; n++)
                    acc[m][n] = fmaf(a[m], b[n], acc[m][n]);
        }
        if (more) {
            const int nb = buf ^ 1;
            float qv = Qs[h0 + lr];
            Rs[nb][lr][lc+0] = fmaxf(p0.x + qv, 0.f);
            Rs[nb][lr][lc+1] = fmaxf(p0.y + qv, 0.f);
            Rs[nb][lr][lc+2] = fmaxf(p0.z + qv, 0.f);
            Rs[nb][lr][lc+3] = fmaxf(p0.w + qv, 0.f);
            Rs[nb][lr][lc+4] = fmaxf(p1.x + qv, 0.f);
            Rs[nb][lr][lc+5] = fmaxf(p1.y + qv, 0.f);
            Rs[nb][lr][lc+6] = fmaxf(p1.z + qv, 0.f);
            Rs[nb][lr][lc+7] = fmaxf(p1.w + qv, 0.f);
            Ws[nb][lr][lc+0] = w0.x; Ws[nb][lr][lc+1] = w0.y;
            Ws[nb][lr][lc+2] = w0.z; Ws[nb][lr][lc+3] = w0.w;
            Ws[nb][lr][lc+4] = w1.x; Ws[nb][lr][lc+5] = w1.y;
            Ws[nb][lr][lc+6] = w1.z; Ws[nb][lr][lc+7] = w1.w;
            __syncthreads();
            buf = nb;
        }
    }

    // write t tile (coalesced float4 pairs)
    const size_t srow0 = (size_t)i*NPT + j0 + ty*8;
#pragma unroll
    for (int m = 0; m < 8; m++) {
        size_t off = (srow0 + m)*HDIM + tx*8;
        *(float4*)&g_T[off]     = make_float4(acc[m][0], acc[m][1], acc[m][2], acc[m][3]);
        *(float4*)&g_T[off + 4] = make_float4(acc[m][4], acc[m][5], acc[m][6], acc[m][7]);
    }

    // per-CTA stats: sum over the 128 samples per k, reduce over ty in smem
    float ts[8], tq[8];
#pragma unroll
    for (int n = 0; n < 8; n++) {
        float s = 0.f, q = 0.f;
#pragma unroll
        for (int m = 0; m < 8; m++) { s += acc[m][n]; q = fmaf(acc[m][n], acc[m][n], q); }
        ts[n] = s; tq[n] = q;
    }
    __syncthreads();   // mainloop done before reusing smem
#pragma unroll
    for (int n = 0; n < 8; n++) { Rs[0][ty][tx*8 + n] = ts[n]; Ws[0][ty][tx*8 + n] = tq[n]; }
    __syncthreads();
    if (ty == 0) {
#pragma unroll
        for (int n = 0; n < 8; n++) {
            float s = 0.f, q = 0.f;
#pragma unroll
            for (int r = 0; r < 16; r++) { s += Rs[0][r][tx*8 + n]; q += Ws[0][r][tx*8 + n]; }
            atomicAdd(&g_tsum[tx*8 + n], s);
            atomicAdd(&g_tsq [tx*8 + n], q);
        }
    }
}

// ---------------- K5: BN2 fold (b2 cancels under normalization) ------------
__global__ void k_bn2(const float* __restrict__ g2, const float* __restrict__ be2) {
    int k = threadIdx.x;   // 128 threads, 1 block
    const float inv = 1.f / (float)NNTOT;
    float m = g_tsum[k] * inv;
    float v = g_tsq[k] * inv - m*m;
    float sc = g2[k] * rsqrtf(v + EPS);
    g_sc2[k]  = sc;
    g_off2[k] = be2[k] - m * sc;
}

// ---------------- K6: pass 2 — logits = relu(bn2(t)) . W3 + b3 -------------
// warp per sample; lane owns 4 consecutive k.
__global__ __launch_bounds__(256) void k_pass2(const float* __restrict__ W3,
                                               const float* __restrict__ b3) {
    const int tid  = threadIdx.x;
    const int warp = tid >> 5, lane = tid & 31;
    const int k = lane * 4;
    const float4 sc4 = *(const float4*)&g_sc2[k];
    const float4 of4 = *(const float4*)&g_off2[k];
    const float4 w34 = *(const float4*)&W3[k];
    const float bb = b3[0];
    size_t s0 = ((size_t)blockIdx.x*8 + warp) * 32;
    for (int it = 0; it < 32; it++) {
        size_t s = s0 + it;
        float4 tv = *(const float4*)&g_T[s*HDIM + k];
        float z0 = fmaxf(fmaf(tv.x, sc4.x, of4.x), 0.f);
        float z1 = fmaxf(fmaf(tv.y, sc4.y, of4.y), 0.f);
        float z2 = fmaxf(fmaf(tv.z, sc4.z, of4.z), 0.f);
        float z3 = fmaxf(fmaf(tv.w, sc4.w, of4.w), 0.f);
        float p = z0*w34.x + z1*w34.y + z2*w34.z + z3*w34.w;
#pragma unroll
        for (int o = 16; o; o >>= 1) p += __shfl_xor_sync(0xffffffffu, p, o);
        if (lane == 0) g_L[s] = p + bb;
    }
}

// ---------------- K7: adj = sigmoid(0.5*(L + L^T)), zero diagonal ----------
__global__ void k_adj(float* __restrict__ out) {
    int idx = blockIdx.x*256 + threadIdx.x;
    int i = idx >> 10, j = idx & 1023;
    float l = 0.5f * (g_L[idx] + g_L[j*NPT + i]);
    out[idx] = (i == j) ? 0.f : 1.f / (1.f + expf(-l));
}

// ---------------- launch ---------------------------------------------------
extern "C" void kernel_launch(void* const* d_in, const int* in_sizes, int n_in,
                              void* d_out, int out_size) {
    (void)in_sizes; (void)n_in; (void)out_size;
    const float* x   = (const float*)d_in[0];
    const float* W1  = (const float*)d_in[1];
    const float* b1  = (const float*)d_in[2];
    const float* W2  = (const float*)d_in[3];
    // d_in[4] = b2 (cancels under BN2 — unused)
    const float* W3  = (const float*)d_in[5];
    const float* b3  = (const float*)d_in[6];
    const float* g1  = (const float*)d_in[7];
    const float* be1 = (const float*)d_in[8];
    const float* g2  = (const float*)d_in[9];
    const float* be2 = (const float*)d_in[10];
    float* out = (float*)d_out;

    k_ab  <<<NPT, FDIM>>>(x, W1);
    k_bn1 <<<HDIM, 256>>>(b1, g1, be1);
    k_prep<<<(NPT*HDIM + 255)/256, 256>>>(W2);
    {
        dim3 grid(NPT/128, NPT);
        k_pass1<<<grid, 256>>>();
    }
    k_bn2 <<<1, HDIM>>>(g2, be2);
    k_pass2<<<NNTOT/256, 256>>>(W3, b3);
    k_adj <<<NNTOT/256, 256>>>(out);
}

// round 15
// speedup vs baseline: 1.2951x; 1.2951x over previous
#include <cuda_runtime.h>
#include <cuda_bf16.h>
#include <cstdint>
#include <math.h>

#define NPT 1024
#define FDIM 128
#define HDIM 128
#define NNTOT (NPT*NPT)
#define EPS 1e-5f

// m16n8k16 row.col bf16 MMA, fp32 accum (base-arch feature, works on sm_103)
#define MMA_BF16(d, a, b) \
    asm volatile("mma.sync.aligned.m16n8k16.row.col.f32.bf16.bf16.f32 " \
        "{%0,%1,%2,%3}, {%4,%5,%6,%7}, {%8,%9}, {%0,%1,%2,%3};" \
        : "+f"((d)[0]), "+f"((d)[1]), "+f"((d)[2]), "+f"((d)[3]) \
        : "r"((a)[0]), "r"((a)[1]), "r"((a)[2]), "r"((a)[3]), \
          "r"((b)[0]), "r"((b)[1]))

// ======================= scratch (device globals) ==========================
__device__ float g_A[NPT*HDIM];
__device__ float g_B[NPT*HDIM];
__device__ float g_Pjh[NPT*HDIM];            // P in [j][h] layout, BN1-folded
__device__ float g_Q[NPT*HDIM];              // [i][h], BN1-folded
__device__ float g_sc1[HDIM], g_off1[HDIM];
__device__ __nv_bfloat16 g_W2hib[HDIM*HDIM]; // W2 hi, row-major [k][h]
__device__ __nv_bfloat16 g_W2lob[HDIM*HDIM]; // W2 lo residual
__device__ float g_tsum[HDIM], g_tsq[HDIM];
__device__ float g_sc2[HDIM], g_off2[HDIM];
__device__ float g_T[(size_t)NNTOT*HDIM];    // 512 MB: t[i*N+j][k]
__device__ float g_L[NNTOT];                 // logits

// dynamic SMEM layout for pass1 — bf16 tiles at 136-bf16 (272 B) row stride
#define RSTRIDE   272                        // bytes per 128-col bf16 row
#define OFF_WHI   0
#define OFF_WLO   34816
#define OFF_RHI   69632
#define OFF_RLO   104448
#define OFF_SS    139264                     // 128 floats: sum
#define OFF_SQ    139776                     // 128 floats: sum of squares
#define SMEM_TOTAL 140288

// ---------------- K1: A = x@Wa^T, B = x@Wb^T -------------------------------
__global__ void k_ab(const float* __restrict__ x, const float* __restrict__ W1) {
    __shared__ float xs[FDIM];
    int j = blockIdx.x;
    int h = threadIdx.x;
    xs[h] = x[j*FDIM + h];
    __syncthreads();
    const float* wr = W1 + h*(2*FDIM);
    float a = 0.f, b = 0.f;
#pragma unroll 8
    for (int f = 0; f < FDIM; f++) {
        float xv = xs[f];
        a = fmaf(xv, wr[f], a);
        b = fmaf(xv, wr[FDIM + f], b);
    }
    g_A[j*HDIM + h] = a;
    g_B[j*HDIM + h] = b;
}

// ---------------- K2: BN1 stats (exact product-grid decomposition) ---------
// mean over (i,j) grid = meanA + meanB + b1 ; var = VarA + VarB (cross = 0)
__global__ void k_bn1(const float* __restrict__ b1, const float* __restrict__ g1,
                      const float* __restrict__ be1) {
    int h = blockIdx.x;
    int t = threadIdx.x;
    float sa = 0.f, sa2 = 0.f, sb = 0.f, sb2 = 0.f;
    for (int j = t; j < NPT; j += 256) {
        float a = g_A[j*HDIM + h]; sa += a; sa2 += a*a;
        float b = g_B[j*HDIM + h]; sb += b; sb2 += b*b;
    }
    __shared__ float red[4][256];
    red[0][t] = sa; red[1][t] = sa2; red[2][t] = sb; red[3][t] = sb2;
    __syncthreads();
    for (int s = 128; s > 0; s >>= 1) {
        if (t < s) {
#pragma unroll
            for (int c = 0; c < 4; c++) red[c][t] += red[c][t + s];
        }
        __syncthreads();
    }
    if (t == 0) {
        float ma = red[0][0] * (1.f/NPT), mb = red[2][0] * (1.f/NPT);
        float va = red[1][0] * (1.f/NPT) - ma*ma;
        float vb = red[3][0] * (1.f/NPT) - mb*mb;
        float m1  = ma + mb + b1[h];
        float sc  = g1[h] * rsqrtf(va + vb + EPS);
        g_sc1[h]  = sc;
        g_off1[h] = (b1[h] - m1) * sc + be1[h];
    }
}

// ---------------- K3: fold BN1 into P/Q; split W2 into bf16 hi/lo ----------
__global__ void k_prep(const float* __restrict__ W2) {
    int idx = blockIdx.x*256 + threadIdx.x;
    if (idx < NPT*HDIM) {
        int h = idx & 127;
        float sc = g_sc1[h];
        g_Pjh[idx] = g_A[idx] * sc;
        g_Q[idx]   = g_B[idx] * sc + g_off1[h];
    }
    if (idx < HDIM*HDIM) {
        float w = W2[idx];
        __nv_bfloat16 hi = __float2bfloat16(w);
        __nv_bfloat16 lo = __float2bfloat16(w - __bfloat162float(hi));
        g_W2hib[idx] = hi;
        g_W2lob[idx] = lo;
    }
    if (idx < HDIM) { g_tsum[idx] = 0.f; g_tsq[idx] = 0.f; }
}

// ---------------- K4: HMMA pass — t = relu(P+Q) @ W2^T (hi/lo split) -------
// CTA: 128 j-rows x 128 k, loops 8 i-values. 8 warps, 32x64 warp tiles.
// Fragment mapping (PTX ISA m16n8k16): g=lane>>2, t4=lane&3.
//  A[r=g(+8)][k=2*t4(+1)(+8)]  B[k=2*t4(+1)(+8)][n=g]  D[r=g(+8)][c=2*t4(+1)]
__global__ __launch_bounds__(256, 1) void k_pass1_mma() {
    extern __shared__ char sm[];
    const int tid = threadIdx.x;
    const int wid = tid >> 5, lane = tid & 31;
    const int g = lane >> 2, t4 = lane & 3;
    const int j0 = blockIdx.x * 128;
    const int ibase = blockIdx.y * 8;
    const int m0 = (wid & 3) * 32;       // warp row base
    const int n0 = (wid >> 2) * 64;      // warp col base

    // ---- stage W2 hi/lo into smem (row n, 272-B stride) ----
    {
        const int row = tid >> 1, half = tid & 1;
        const uint4* shi = (const uint4*)(g_W2hib + row*128 + half*64);
        const uint4* slo = (const uint4*)(g_W2lob + row*128 + half*64);
        uint4* dhi = (uint4*)(sm + OFF_WHI + row*RSTRIDE + half*128);
        uint4* dlo = (uint4*)(sm + OFF_WLO + row*RSTRIDE + half*128);
#pragma unroll
        for (int v = 0; v < 8; v++) { dhi[v] = shi[v]; dlo[v] = slo[v]; }
    }
    if (tid < 128) {
        ((float*)(sm + OFF_SS))[tid] = 0.f;
        ((float*)(sm + OFF_SQ))[tid] = 0.f;
    }

    // r-build mapping: thread -> (row j, 64-col half)
    const int brow = tid >> 1, bhalf = tid & 1;
    char* rhi_p = sm + OFF_RHI + brow*RSTRIDE + bhalf*128;
    char* rlo_p = sm + OFF_RLO + brow*RSTRIDE + bhalf*128;
    const float* Prow = g_Pjh + (size_t)(j0 + brow) * HDIM + bhalf * 64;

    // fragment base byte offsets (conflict-free: bank = 4g+t4 = lane)
    const uint32_t aoff0 = (uint32_t)(m0 + g) * RSTRIDE + (uint32_t)t4 * 4;
    const uint32_t boff0 = (uint32_t)(n0 + g) * RSTRIDE + (uint32_t)t4 * 4;

    // stats accumulators (per thread, col pair per n-tile)
    float se[8], so[8], qe[8], qo[8];
#pragma unroll
    for (int nt = 0; nt < 8; nt++) { se[nt]=0.f; so[nt]=0.f; qe[nt]=0.f; qo[nt]=0.f; }

    for (int it = 0; it < 8; it++) {
        const int i = ibase + it;
        float acc[2][8][4];
#pragma unroll
        for (int mt = 0; mt < 2; mt++)
#pragma unroll
            for (int nt = 0; nt < 8; nt++)
#pragma unroll
                for (int c = 0; c < 4; c++) acc[mt][nt][c] = 0.f;

        __syncthreads();   // prev-iter r reads done (iter0: W2/stats staged)

        // ---- build r = relu(P+Q), split hi/lo bf16 ----
        {
            const float* Qrow = g_Q + (size_t)i * HDIM + bhalf * 64;
#pragma unroll
            for (int v = 0; v < 16; v++) {
                float4 p = *(const float4*)(Prow + 4*v);
                float4 q = *(const float4*)(Qrow + 4*v);
                float x0 = fmaxf(p.x + q.x, 0.f), x1 = fmaxf(p.y + q.y, 0.f);
                float x2 = fmaxf(p.z + q.z, 0.f), x3 = fmaxf(p.w + q.w, 0.f);
                __nv_bfloat162 h01 = __floats2bfloat162_rn(x0, x1);
                __nv_bfloat162 h23 = __floats2bfloat162_rn(x2, x3);
                __nv_bfloat162 l01 = __floats2bfloat162_rn(x0 - __low2float(h01),
                                                           x1 - __high2float(h01));
                __nv_bfloat162 l23 = __floats2bfloat162_rn(x2 - __low2float(h23),
                                                           x3 - __high2float(h23));
                *(__nv_bfloat162*)(rhi_p + v*8)     = h01;
                *(__nv_bfloat162*)(rhi_p + v*8 + 4) = h23;
                *(__nv_bfloat162*)(rlo_p + v*8)     = l01;
                *(__nv_bfloat162*)(rlo_p + v*8 + 4) = l23;
            }
        }
        __syncthreads();   // r visible

        // ---- 3-term HMMA mainloop: rhi*whi + rhi*wlo + rlo*whi ----
#pragma unroll
        for (int term = 0; term < 3; term++) {
            const char* As = sm + (term == 2 ? OFF_RLO : OFF_RHI);
            const char* Bs = sm + (term == 1 ? OFF_WLO : OFF_WHI);
#pragma unroll
            for (int ks = 0; ks < 8; ks++) {
                const char* pa = As + aoff0 + ks*32;
                const char* pb = Bs + boff0 + ks*32;
                uint32_t a[2][4], b[8][2];
#pragma unroll
                for (int mt = 0; mt < 2; mt++) {
                    const char* p = pa + mt*(16*RSTRIDE);
                    a[mt][0] = *(const uint32_t*)(p);
                    a[mt][1] = *(const uint32_t*)(p + 8*RSTRIDE);
                    a[mt][2] = *(const uint32_t*)(p + 16);
                    a[mt][3] = *(const uint32_t*)(p + 8*RSTRIDE + 16);
                }
#pragma unroll
                for (int nt = 0; nt < 8; nt++) {
                    const char* p = pb + nt*(8*RSTRIDE);
                    b[nt][0] = *(const uint32_t*)(p);
                    b[nt][1] = *(const uint32_t*)(p + 16);
                }
#pragma unroll
                for (int mt = 0; mt < 2; mt++)
#pragma unroll
                    for (int nt = 0; nt < 8; nt++)
                        MMA_BF16(acc[mt][nt], a[mt], b[nt]);
            }
        }

        // ---- write t tile straight from fragments (full 32B sectors) ----
#pragma unroll
        for (int mt = 0; mt < 2; mt++) {
            const size_t base =
                ((size_t)i*NPT + j0 + m0 + mt*16 + g) * HDIM + n0 + 2*t4;
#pragma unroll
            for (int nt = 0; nt < 8; nt++) {
                *(float2*)&g_T[base + nt*8] =
                    make_float2(acc[mt][nt][0], acc[mt][nt][1]);
                *(float2*)&g_T[base + 8*HDIM + nt*8] =
                    make_float2(acc[mt][nt][2], acc[mt][nt][3]);
            }
        }

        // ---- accumulate BN2 stats in registers ----
#pragma unroll
        for (int nt = 0; nt < 8; nt++) {
            float e0 = acc[0][nt][0], e1 = acc[0][nt][2];
            float e2 = acc[1][nt][0], e3 = acc[1][nt][2];
            float o0 = acc[0][nt][1], o1 = acc[0][nt][3];
            float o2 = acc[1][nt][1], o3 = acc[1][nt][3];
            se[nt] += (e0 + e1) + (e2 + e3);
            so[nt] += (o0 + o1) + (o2 + o3);
            qe[nt] += e0*e0 + e1*e1 + e2*e2 + e3*e3;
            qo[nt] += o0*o0 + o1*o1 + o2*o2 + o3*o3;
        }
    }

    // ---- reduce stats: shfl over row-groups, smem, then global ----
#pragma unroll
    for (int nt = 0; nt < 8; nt++) {
#pragma unroll
        for (int mk = 4; mk <= 16; mk <<= 1) {
            se[nt] += __shfl_xor_sync(0xffffffffu, se[nt], mk);
            so[nt] += __shfl_xor_sync(0xffffffffu, so[nt], mk);
            qe[nt] += __shfl_xor_sync(0xffffffffu, qe[nt], mk);
            qo[nt] += __shfl_xor_sync(0xffffffffu, qo[nt], mk);
        }
    }
    float* sS = (float*)(sm + OFF_SS);
    float* sQ = (float*)(sm + OFF_SQ);
    if (lane < 4) {
#pragma unroll
        for (int nt = 0; nt < 8; nt++) {
            int c = n0 + nt*8 + 2*lane;
            atomicAdd(&sS[c],   se[nt]);
            atomicAdd(&sS[c+1], so[nt]);
            atomicAdd(&sQ[c],   qe[nt]);
            atomicAdd(&sQ[c+1], qo[nt]);
        }
    }
    __syncthreads();
    if (tid < 128) {
        atomicAdd(&g_tsum[tid], sS[tid]);
        atomicAdd(&g_tsq [tid], sQ[tid]);
    }
}

// ---------------- K5: BN2 fold (b2 cancels) --------------------------------
__global__ void k_bn2(const float* __restrict__ g2, const float* __restrict__ be2) {
    int k = threadIdx.x;
    const float inv = 1.f / (float)NNTOT;
    float m = g_tsum[k] * inv;
    float v = g_tsq[k] * inv - m*m;
    float sc = g2[k] * rsqrtf(v + EPS);
    g_sc2[k]  = sc;
    g_off2[k] = be2[k] - m * sc;
}

// ---------------- K6: pass 2 — logits = relu(bn2(t)) . W3 + b3 -------------
__global__ __launch_bounds__(256) void k_pass2(const float* __restrict__ W3,
                                               const float* __restrict__ b3) {
    const int tid  = threadIdx.x;
    const int warp = tid >> 5, lane = tid & 31;
    const int k = lane * 4;
    const float4 sc4 = *(const float4*)&g_sc2[k];
    const float4 of4 = *(const float4*)&g_off2[k];
    const float4 w34 = *(const float4*)&W3[k];
    const float bb = b3[0];
    size_t s0 = ((size_t)blockIdx.x*8 + warp) * 32;
    for (int it = 0; it < 32; it++) {
        size_t s = s0 + it;
        float4 tv = *(const float4*)&g_T[s*HDIM + k];
        float z0 = fmaxf(fmaf(tv.x, sc4.x, of4.x), 0.f);
        float z1 = fmaxf(fmaf(tv.y, sc4.y, of4.y), 0.f);
        float z2 = fmaxf(fmaf(tv.z, sc4.z, of4.z), 0.f);
        float z3 = fmaxf(fmaf(tv.w, sc4.w, of4.w), 0.f);
        float p = z0*w34.x + z1*w34.y + z2*w34.z + z3*w34.w;
#pragma unroll
        for (int o = 16; o; o >>= 1) p += __shfl_xor_sync(0xffffffffu, p, o);
        if (lane == 0) g_L[s] = p + bb;
    }
}

// ---------------- K7: adj = sigmoid(0.5*(L + L^T)), zero diagonal ----------
__global__ void k_adj(float* __restrict__ out) {
    int idx = blockIdx.x*256 + threadIdx.x;
    int i = idx >> 10, j = idx & 1023;
    float l = 0.5f * (g_L[idx] + g_L[j*NPT + i]);
    out[idx] = (i == j) ? 0.f : 1.f / (1.f + expf(-l));
}

// ---------------- launch ---------------------------------------------------
extern "C" void kernel_launch(void* const* d_in, const int* in_sizes, int n_in,
                              void* d_out, int out_size) {
    (void)in_sizes; (void)n_in; (void)out_size;
    const float* x   = (const float*)d_in[0];
    const float* W1  = (const float*)d_in[1];
    const float* b1  = (const float*)d_in[2];
    const float* W2  = (const float*)d_in[3];
    // d_in[4] = b2 (cancels under BN2 — unused)
    const float* W3  = (const float*)d_in[5];
    const float* b3  = (const float*)d_in[6];
    const float* g1  = (const float*)d_in[7];
    const float* be1 = (const float*)d_in[8];
    const float* g2  = (const float*)d_in[9];
    const float* be2 = (const float*)d_in[10];
    float* out = (float*)d_out;

    cudaFuncSetAttribute(k_pass1_mma, cudaFuncAttributeMaxDynamicSharedMemorySize,
                         SMEM_TOTAL);

    k_ab  <<<NPT, FDIM>>>(x, W1);
    k_bn1 <<<HDIM, 256>>>(b1, g1, be1);
    k_prep<<<(NPT*HDIM + 255)/256, 256>>>(W2);
    {
        dim3 grid(NPT/128, NPT/8);
        k_pass1_mma<<<grid, 256, SMEM_TOTAL>>>();
    }
    k_bn2 <<<1, HDIM>>>(g2, be2);
    k_pass2<<<NNTOT/256, 256>>>(W3, b3);
    k_adj <<<NNTOT/256, 256>>>(out);
}